// round 2
// baseline (speedup 1.0000x reference)
#include <cuda_runtime.h>

#define Bb 2
#define Hh 16
#define Ss 2048
#define Dd 128
#define BM 64
#define BN 64
#define NT 256
#define KSTRIDE 132   // 128 + 4 pad: kills K-load bank conflicts, keeps 16B align
#define PSTRIDE 68    // 64 + 4 pad
#define SMEM_FLOATS (2*BM*KSTRIDE + BM*PSTRIDE)
#define SMEM_BYTES (SMEM_FLOATS*4)

__device__ int g_len[Bb];
__device__ int g_off;

// Derive per-batch valid lengths from the padding mask, robust to the mask's
// storage width (bool->uint8 vs int32/float32). lengths >= S/2 guarantees
// element 1 is "true": byte[1]!=0 => 1-byte elements; ==0 => 4-byte elements.
__global__ void prep_kernel(const unsigned char* __restrict__ mask, const int* offp) {
    int b = blockIdx.x;
    __shared__ int cnt;
    if (threadIdx.x == 0) cnt = 0;
    __syncthreads();
    bool w4 = (mask[1] == 0);
    int local = 0;
    for (int j = threadIdx.x; j < Ss; j += blockDim.x) {
        bool valid;
        if (w4) valid = (((const unsigned int*)mask)[(size_t)b * Ss + j] != 0u);
        else    valid = (mask[(size_t)b * Ss + j] != 0);
        local += valid ? 1 : 0;
    }
    atomicAdd(&cnt, local);
    __syncthreads();
    if (threadIdx.x == 0) {
        g_len[b] = cnt;
        if (b == 0) g_off = offp ? offp[0] : 0;
    }
}

__global__ __launch_bounds__(NT, 2)
void attend_kernel(const float* __restrict__ Q, const float* __restrict__ K,
                   const float* __restrict__ V, const float* __restrict__ Bias,
                   float* __restrict__ Out) {
    extern __shared__ float smem[];
    float* Qs = smem;                    // [64][132]
    float* Ks = smem + BM * KSTRIDE;     // [64][132], reused for V
    float* Ps = smem + 2 * BM * KSTRIDE; // [64][68]

    const int tid = threadIdx.x;
    const int ty = tid >> 4;   // 0..15 -> q-row group
    const int tx = tid & 15;   // 0..15 -> key-col / out-col group
    const int bh = blockIdx.y;
    const int b = bh / Hh;
    const int h = bh - b * Hh;
    const int q0 = blockIdx.x * BM;

    const int L   = g_len[b];
    const int off = g_off;

    const float* qb = Q + ((size_t)bh * Ss + q0) * Dd;
    const float* kb = K + (size_t)bh * Ss * Dd;
    const float* vb = V + (size_t)bh * Ss * Dd;
    const float* bb = Bias + (size_t)h * Ss * Ss;
    float* ob = Out + ((size_t)bh * Ss + q0) * Dd;

    // Load Q tile (64 x 128), float4 coalesced
    #pragma unroll
    for (int t = tid; t < BM * (Dd / 4); t += NT) {
        int r = t >> 5, c4 = t & 31;
        float4 val = ((const float4*)(qb + (size_t)r * Dd))[c4];
        *(float4*)&Qs[r * KSTRIDE + c4 * 4] = val;
    }

    float m[4], l[4], O[4][8];
    #pragma unroll
    for (int a = 0; a < 4; a++) {
        m[a] = -1e30f; l[a] = 0.f;
        #pragma unroll
        for (int j = 0; j < 8; j++) O[a][j] = 0.f;
    }

    // causal + padding tile bound: keys j <= i - off, j < L
    int maxj = q0 + BM - 1 - off;
    if (maxj > L - 1) maxj = L - 1;
    const int ntiles = (maxj >= 0) ? (maxj / BN + 1) : 0;

    const float scale = 0.08838834764831845f;  // 128^-0.5

    for (int t = 0; t < ntiles; ++t) {
        const int n0 = t * BN;
        __syncthreads();  // previous iter done reading Ks/Ps
        // Load K tile
        #pragma unroll
        for (int tt = tid; tt < BN * (Dd / 4); tt += NT) {
            int r = tt >> 5, c4 = tt & 31;
            float4 val = ((const float4*)(kb + (size_t)(n0 + r) * Dd))[c4];
            *(float4*)&Ks[r * KSTRIDE + c4 * 4] = val;
        }
        __syncthreads();

        // S = Q @ K^T (register-tiled 4x4, vectorized over d)
        float acc[4][4];
        #pragma unroll
        for (int a = 0; a < 4; a++)
            #pragma unroll
            for (int c = 0; c < 4; c++) acc[a][c] = 0.f;

        #pragma unroll 8
        for (int d = 0; d < Dd; d += 4) {
            float4 qv[4], kv[4];
            #pragma unroll
            for (int a = 0; a < 4; a++)
                qv[a] = *(const float4*)&Qs[(ty + 16 * a) * KSTRIDE + d];
            #pragma unroll
            for (int c = 0; c < 4; c++)
                kv[c] = *(const float4*)&Ks[(tx + 16 * c) * KSTRIDE + d];
            #pragma unroll
            for (int a = 0; a < 4; a++)
                #pragma unroll
                for (int c = 0; c < 4; c++) {
                    acc[a][c] = fmaf(qv[a].x, kv[c].x, acc[a][c]);
                    acc[a][c] = fmaf(qv[a].y, kv[c].y, acc[a][c]);
                    acc[a][c] = fmaf(qv[a].z, kv[c].z, acc[a][c]);
                    acc[a][c] = fmaf(qv[a].w, kv[c].w, acc[a][c]);
                }
        }

        const bool full = (n0 + BN - 1 <= q0 - off) && (n0 + BN <= L);

        float s[4][4];
        #pragma unroll
        for (int a = 0; a < 4; a++) {
            const int i = q0 + ty + 16 * a;
            #pragma unroll
            for (int c = 0; c < 4; c++) {
                const int j = n0 + tx + 16 * c;
                if (full || ((j <= i - off) && (j < L)))
                    s[a][c] = acc[a][c] * scale + __ldg(&bb[(size_t)i * Ss + j]);
                else
                    s[a][c] = -1e30f;
            }
        }

        // Online softmax (row spread over 16 lanes; width-16 shuffles)
        #pragma unroll
        for (int a = 0; a < 4; a++) {
            float mx = fmaxf(fmaxf(s[a][0], s[a][1]), fmaxf(s[a][2], s[a][3]));
            #pragma unroll
            for (int w = 8; w >= 1; w >>= 1)
                mx = fmaxf(mx, __shfl_xor_sync(0xFFFFFFFFu, mx, w, 16));
            float mnew  = fmaxf(m[a], mx);
            float alpha = __expf(m[a] - mnew);
            float sum = 0.f;
            #pragma unroll
            for (int c = 0; c < 4; c++) {
                float p = __expf(s[a][c] - mnew);
                sum += p;
                Ps[(ty + 16 * a) * PSTRIDE + tx + 16 * c] = p;
            }
            #pragma unroll
            for (int w = 8; w >= 1; w >>= 1)
                sum += __shfl_xor_sync(0xFFFFFFFFu, sum, w, 16);
            l[a] = l[a] * alpha + sum;
            m[a] = mnew;
            #pragma unroll
            for (int j = 0; j < 8; j++) O[a][j] *= alpha;
        }

        __syncthreads();  // Ps fully written; Ks free
        // Load V tile into the K buffer
        #pragma unroll
        for (int tt = tid; tt < BN * (Dd / 4); tt += NT) {
            int r = tt >> 5, c4 = tt & 31;
            float4 val = ((const float4*)(vb + (size_t)(n0 + r) * Dd))[c4];
            *(float4*)&Ks[r * KSTRIDE + c4 * 4] = val;
        }
        __syncthreads();

        // O += P @ V (4 keys per step, float4 P loads)
        #pragma unroll 4
        for (int n4 = 0; n4 < BN; n4 += 4) {
            float pr[4][4];
            #pragma unroll
            for (int a = 0; a < 4; a++) {
                float4 p4 = *(const float4*)&Ps[(ty + 16 * a) * PSTRIDE + n4];
                pr[a][0] = p4.x; pr[a][1] = p4.y; pr[a][2] = p4.z; pr[a][3] = p4.w;
            }
            #pragma unroll
            for (int nn = 0; nn < 4; nn++) {
                float vv[8];
                #pragma unroll
                for (int j = 0; j < 8; j++)
                    vv[j] = Ks[(n4 + nn) * KSTRIDE + tx + 16 * j];
                #pragma unroll
                for (int a = 0; a < 4; a++)
                    #pragma unroll
                    for (int j = 0; j < 8; j++)
                        O[a][j] = fmaf(pr[a][nn], vv[j], O[a][j]);
            }
        }
    }

    // Normalize + write out
    #pragma unroll
    for (int a = 0; a < 4; a++) {
        float inv = (l[a] > 0.f) ? (1.f / l[a]) : 0.f;
        const int i = ty + 16 * a;
        #pragma unroll
        for (int j = 0; j < 8; j++)
            ob[(size_t)i * Dd + tx + 16 * j] = O[a][j] * inv;
    }
}

extern "C" void kernel_launch(void* const* d_in, const int* in_sizes, int n_in,
                              void* d_out, int out_size) {
    const float* q = (const float*)d_in[0];
    const float* k = (const float*)d_in[1];
    const float* v = (const float*)d_in[2];
    const unsigned char* mask = (const unsigned char*)d_in[3];
    const float* bias = (const float*)d_in[4];
    const int* off = (n_in > 5) ? (const int*)d_in[5] : nullptr;
    float* out = (float*)d_out;

    cudaFuncSetAttribute(attend_kernel,
                         cudaFuncAttributeMaxDynamicSharedMemorySize, SMEM_BYTES);

    prep_kernel<<<Bb, 256>>>(mask, off);
    dim3 grid(Ss / BM, Bb * Hh);
    attend_kernel<<<grid, NT, SMEM_BYTES>>>(q, k, v, bias, out);
}

// round 4
// speedup vs baseline: 2.3481x; 2.3481x over previous
#include <cuda_runtime.h>
#include <cuda_bf16.h>
#include <string.h>

#define Bb 2
#define Hh 16
#define Ss 2048
#define Dd 128
#define BM 128
#define BN 64
#define NT 256

// smem strides in bf16 elements (pad 8 -> conflict-free ldmatrix rows)
#define SQ 136
#define SK 136
#define SP 72

// smem offsets in bf16 elements
#define OFF_QH 0
#define OFF_QL 17408            // 128*136
#define OFF_KH 34816
#define OFF_KL 43520            // +64*136
#define OFF_VH 52224
#define OFF_VL 60928
#define OFF_PH 69632
#define OFF_PL 78848            // +128*72
#define SMEM_ELEMS 88064
#define SMEM_BYTES (SMEM_ELEMS*2)  // 176128

__device__ int g_len[Bb];
__device__ int g_off;

__global__ void prep_kernel(const unsigned char* __restrict__ mask, const int* offp) {
    int b = blockIdx.x;
    __shared__ int cnt;
    if (threadIdx.x == 0) cnt = 0;
    __syncthreads();
    bool w4 = (mask[1] == 0);
    int local = 0;
    for (int j = threadIdx.x; j < Ss; j += blockDim.x) {
        bool valid;
        if (w4) valid = (((const unsigned int*)mask)[(size_t)b * Ss + j] != 0u);
        else    valid = (mask[(size_t)b * Ss + j] != 0);
        local += valid ? 1 : 0;
    }
    atomicAdd(&cnt, local);
    __syncthreads();
    if (threadIdx.x == 0) {
        g_len[b] = cnt;
        if (b == 0) g_off = offp ? offp[0] : 0;
    }
}

__device__ __forceinline__ void split_pack(float x, float y, unsigned &hi, unsigned &lo) {
    __nv_bfloat162 hv = __floats2bfloat162_rn(x, y);
    float2 hf = __bfloat1622float2(hv);
    __nv_bfloat162 lv = __floats2bfloat162_rn(x - hf.x, y - hf.y);
    memcpy(&hi, &hv, 4);
    memcpy(&lo, &lv, 4);
}

#define LDSM4(r0,r1,r2,r3,addr) \
    asm volatile("ldmatrix.sync.aligned.m8n8.x4.shared.b16 {%0,%1,%2,%3}, [%4];\n" \
        : "=r"(r0),"=r"(r1),"=r"(r2),"=r"(r3) : "r"(addr))
#define LDSM4T(r0,r1,r2,r3,addr) \
    asm volatile("ldmatrix.sync.aligned.m8n8.x4.trans.shared.b16 {%0,%1,%2,%3}, [%4];\n" \
        : "=r"(r0),"=r"(r1),"=r"(r2),"=r"(r3) : "r"(addr))
#define MMA_BF16(c,a,b0,b1) \
    asm volatile("mma.sync.aligned.m16n8k16.row.col.f32.bf16.bf16.f32 " \
        "{%0,%1,%2,%3}, {%4,%5,%6,%7}, {%8,%9}, {%0,%1,%2,%3};\n" \
        : "+f"(c[0]),"+f"(c[1]),"+f"(c[2]),"+f"(c[3]) \
        : "r"(a[0]),"r"(a[1]),"r"(a[2]),"r"(a[3]),"r"(b0),"r"(b1))

__global__ __launch_bounds__(NT, 1)
void attend_kernel(const float* __restrict__ Q, const float* __restrict__ K,
                   const float* __restrict__ V, const float* __restrict__ Bias,
                   float* __restrict__ Out) {
    extern __shared__ unsigned short sm16[];

    const int tid = threadIdx.x;
    const int lane = tid & 31, w = tid >> 5;
    const int g = lane >> 2, t4 = lane & 3;
    const int lm = lane & 7, sel = lane >> 3;  // 0..3
    const int m0 = w * 16;

    const int bh = blockIdx.y;
    const int b = bh / Hh;
    const int h = bh - b * Hh;
    const int q0 = (gridDim.x - 1 - blockIdx.x) * BM;  // heavy CTAs first

    const int L = g_len[b];
    const int off = g_off;

    const float* qb = Q + ((size_t)bh * Ss + q0) * Dd;
    const float* kb = K + (size_t)bh * Ss * Dd;
    const float* vb = V + (size_t)bh * Ss * Dd;
    const float* bb = Bias + (size_t)h * Ss * Ss;
    float* ob = Out + ((size_t)bh * Ss + q0) * Dd;

    // ---- stage Q (128 x 128) as bf16 hi/lo ----
    #pragma unroll 4
    for (int t = tid; t < BM * (Dd / 4); t += NT) {
        int r = t >> 5, c4 = t & 31;
        float4 v = ((const float4*)(qb + (size_t)r * Dd))[c4];
        unsigned h0, l0, h1, l1;
        split_pack(v.x, v.y, h0, l0);
        split_pack(v.z, v.w, h1, l1);
        int base = r * SQ + c4 * 4;
        *(unsigned*)&sm16[OFF_QH + base]     = h0;
        *(unsigned*)&sm16[OFF_QH + base + 2] = h1;
        *(unsigned*)&sm16[OFF_QL + base]     = l0;
        *(unsigned*)&sm16[OFF_QL + base + 2] = l1;
    }

    // fragment base addresses (bytes)
    const unsigned smemB = (unsigned)__cvta_generic_to_shared(sm16);
    const int rowA = m0 + lm + (sel & 1) * 8;          // A rows (Q / P)
    const int rowBK = lm + ((sel & 2) >> 1) * 8;       // K rows within nfrag-pair
    const int rowBV = lm + (sel & 1) * 8;              // V key rows within kstep
    const unsigned selA16 = ((sel & 2) >> 1) * 16;     // A col byte offset
    const unsigned selB16 = (sel & 1) * 16;            // B(K) col byte offset

    const unsigned aQH = smemB + (OFF_QH + rowA * SQ) * 2 + selA16;
    const unsigned aQL = smemB + (OFF_QL + rowA * SQ) * 2 + selA16;
    const unsigned aPH = smemB + (OFF_PH + rowA * SP) * 2 + selA16;
    const unsigned aPL = smemB + (OFF_PL + rowA * SP) * 2 + selA16;
    const unsigned bKH = smemB + (OFF_KH + rowBK * SK) * 2 + selB16;
    const unsigned bKL = smemB + (OFF_KL + rowBK * SK) * 2 + selB16;
    const unsigned bVH = smemB + (OFF_VH + rowBV * SK) * 2 + selA16;
    const unsigned bVL = smemB + (OFF_VL + rowBV * SK) * 2 + selA16;

    float o[16][4];
    #pragma unroll
    for (int nf = 0; nf < 16; nf++)
        #pragma unroll
        for (int c = 0; c < 4; c++) o[nf][c] = 0.f;
    float mrow0 = -1e30f, mrow1 = -1e30f, lrow0 = 0.f, lrow1 = 0.f;

    const int i0 = q0 + m0 + g;
    const int i1 = i0 + 8;

    int maxj = q0 + BM - 1 - off;
    if (maxj > L - 1) maxj = L - 1;
    const int ntiles = (maxj >= 0) ? (maxj / BN + 1) : 0;

    const float scale = 0.08838834764831845f;  // 128^-0.5

    for (int t = 0; t < ntiles; ++t) {
        const int n0 = t * BN;
        __syncthreads();  // everyone done reading K/V of previous tile

        // ---- stage K and V tiles (64 x 128) hi/lo ----
        #pragma unroll 4
        for (int tt = tid; tt < BN * (Dd / 4); tt += NT) {
            int r = tt >> 5, c4 = tt & 31;
            float4 kv = ((const float4*)(kb + (size_t)(n0 + r) * Dd))[c4];
            float4 vv = ((const float4*)(vb + (size_t)(n0 + r) * Dd))[c4];
            unsigned h0, l0, h1, l1;
            int base = r * SK + c4 * 4;
            split_pack(kv.x, kv.y, h0, l0); split_pack(kv.z, kv.w, h1, l1);
            *(unsigned*)&sm16[OFF_KH + base]     = h0;
            *(unsigned*)&sm16[OFF_KH + base + 2] = h1;
            *(unsigned*)&sm16[OFF_KL + base]     = l0;
            *(unsigned*)&sm16[OFF_KL + base + 2] = l1;
            split_pack(vv.x, vv.y, h0, l0); split_pack(vv.z, vv.w, h1, l1);
            *(unsigned*)&sm16[OFF_VH + base]     = h0;
            *(unsigned*)&sm16[OFF_VH + base + 2] = h1;
            *(unsigned*)&sm16[OFF_VL + base]     = l0;
            *(unsigned*)&sm16[OFF_VL + base + 2] = l1;
        }
        __syncthreads();

        // ---- S = Q @ K^T via bf16-split mma ----
        float acc[8][4];
        #pragma unroll
        for (int nf = 0; nf < 8; nf++)
            #pragma unroll
            for (int c = 0; c < 4; c++) acc[nf][c] = 0.f;

        #pragma unroll
        for (int kk = 0; kk < 8; kk++) {
            unsigned ah[4], al[4];
            LDSM4(ah[0], ah[1], ah[2], ah[3], aQH + kk * 32);
            LDSM4(al[0], al[1], al[2], al[3], aQL + kk * 32);
            #pragma unroll
            for (int nf2 = 0; nf2 < 4; nf2++) {
                unsigned bhr[4], blr[4];
                const unsigned boff = nf2 * (16 * SK * 2) + kk * 32;
                LDSM4(bhr[0], bhr[1], bhr[2], bhr[3], bKH + boff);
                LDSM4(blr[0], blr[1], blr[2], blr[3], bKL + boff);
                MMA_BF16(acc[2 * nf2],     ah, bhr[0], bhr[1]);
                MMA_BF16(acc[2 * nf2],     ah, blr[0], blr[1]);
                MMA_BF16(acc[2 * nf2],     al, bhr[0], bhr[1]);
                MMA_BF16(acc[2 * nf2 + 1], ah, bhr[2], bhr[3]);
                MMA_BF16(acc[2 * nf2 + 1], ah, blr[2], blr[3]);
                MMA_BF16(acc[2 * nf2 + 1], al, bhr[2], bhr[3]);
            }
        }

        // ---- scale + bias + mask ----
        const bool full = (n0 + BN - 1 <= q0 - off) && (n0 + BN <= L);
        #pragma unroll
        for (int nf = 0; nf < 8; nf++) {
            const int j0 = n0 + nf * 8 + 2 * t4;
            float2 bi0 = __ldg((const float2*)(bb + (size_t)i0 * Ss + j0));
            float2 bi1 = __ldg((const float2*)(bb + (size_t)i1 * Ss + j0));
            if (full) {
                acc[nf][0] = acc[nf][0] * scale + bi0.x;
                acc[nf][1] = acc[nf][1] * scale + bi0.y;
                acc[nf][2] = acc[nf][2] * scale + bi1.x;
                acc[nf][3] = acc[nf][3] * scale + bi1.y;
            } else {
                acc[nf][0] = (j0     <= i0 - off && j0     < L) ? acc[nf][0] * scale + bi0.x : -1e30f;
                acc[nf][1] = (j0 + 1 <= i0 - off && j0 + 1 < L) ? acc[nf][1] * scale + bi0.y : -1e30f;
                acc[nf][2] = (j0     <= i1 - off && j0     < L) ? acc[nf][2] * scale + bi1.x : -1e30f;
                acc[nf][3] = (j0 + 1 <= i1 - off && j0 + 1 < L) ? acc[nf][3] * scale + bi1.y : -1e30f;
            }
        }

        // ---- online softmax (rows private to quad groups) ----
        float mx0 = acc[0][0], mx1 = acc[0][2];
        #pragma unroll
        for (int nf = 0; nf < 8; nf++) {
            mx0 = fmaxf(mx0, fmaxf(acc[nf][0], acc[nf][1]));
            mx1 = fmaxf(mx1, fmaxf(acc[nf][2], acc[nf][3]));
        }
        mx0 = fmaxf(mx0, __shfl_xor_sync(0xFFFFFFFFu, mx0, 1));
        mx0 = fmaxf(mx0, __shfl_xor_sync(0xFFFFFFFFu, mx0, 2));
        mx1 = fmaxf(mx1, __shfl_xor_sync(0xFFFFFFFFu, mx1, 1));
        mx1 = fmaxf(mx1, __shfl_xor_sync(0xFFFFFFFFu, mx1, 2));
        const float mn0 = fmaxf(mrow0, mx0);
        const float mn1 = fmaxf(mrow1, mx1);
        const float alpha0 = __expf(mrow0 - mn0);
        const float alpha1 = __expf(mrow1 - mn1);
        float sum0 = 0.f, sum1 = 0.f;

        #pragma unroll
        for (int nf = 0; nf < 8; nf++) {
            float p00 = __expf(acc[nf][0] - mn0);
            float p01 = __expf(acc[nf][1] - mn0);
            float p10 = __expf(acc[nf][2] - mn1);
            float p11 = __expf(acc[nf][3] - mn1);
            sum0 += p00 + p01;
            sum1 += p10 + p11;
            unsigned hi, lo;
            const int pc = nf * 8 + 2 * t4;
            split_pack(p00, p01, hi, lo);
            *(unsigned*)&sm16[OFF_PH + (m0 + g) * SP + pc] = hi;
            *(unsigned*)&sm16[OFF_PL + (m0 + g) * SP + pc] = lo;
            split_pack(p10, p11, hi, lo);
            *(unsigned*)&sm16[OFF_PH + (m0 + g + 8) * SP + pc] = hi;
            *(unsigned*)&sm16[OFF_PL + (m0 + g + 8) * SP + pc] = lo;
        }
        sum0 += __shfl_xor_sync(0xFFFFFFFFu, sum0, 1);
        sum0 += __shfl_xor_sync(0xFFFFFFFFu, sum0, 2);
        sum1 += __shfl_xor_sync(0xFFFFFFFFu, sum1, 1);
        sum1 += __shfl_xor_sync(0xFFFFFFFFu, sum1, 2);
        lrow0 = lrow0 * alpha0 + sum0;
        lrow1 = lrow1 * alpha1 + sum1;
        mrow0 = mn0; mrow1 = mn1;

        #pragma unroll
        for (int nf = 0; nf < 16; nf++) {
            o[nf][0] *= alpha0; o[nf][1] *= alpha0;
            o[nf][2] *= alpha1; o[nf][3] *= alpha1;
        }
        __syncwarp();  // P visible within warp

        // ---- O += P @ V via bf16-split mma (V loaded transposed via ldmatrix) ----
        #pragma unroll
        for (int kk = 0; kk < 4; kk++) {
            unsigned ah[4], al[4];
            LDSM4(ah[0], ah[1], ah[2], ah[3], aPH + kk * 32);
            LDSM4(al[0], al[1], al[2], al[3], aPL + kk * 32);
            #pragma unroll
            for (int nf2 = 0; nf2 < 8; nf2++) {
                unsigned bhr[4], blr[4];
                const unsigned boff = kk * (16 * SK * 2) + nf2 * 32;
                LDSM4T(bhr[0], bhr[1], bhr[2], bhr[3], bVH + boff);
                LDSM4T(blr[0], blr[1], blr[2], blr[3], bVL + boff);
                MMA_BF16(o[2 * nf2],     ah, bhr[0], bhr[1]);
                MMA_BF16(o[2 * nf2],     ah, blr[0], blr[1]);
                MMA_BF16(o[2 * nf2],     al, bhr[0], bhr[1]);
                MMA_BF16(o[2 * nf2 + 1], ah, bhr[2], bhr[3]);
                MMA_BF16(o[2 * nf2 + 1], ah, blr[2], blr[3]);
                MMA_BF16(o[2 * nf2 + 1], al, bhr[2], bhr[3]);
            }
        }
    }

    // ---- normalize + write ----
    const float inv0 = (lrow0 > 0.f) ? (1.f / lrow0) : 0.f;
    const float inv1 = (lrow1 > 0.f) ? (1.f / lrow1) : 0.f;
    float* o0 = ob + (size_t)(m0 + g) * Dd + 2 * t4;
    float* o1 = ob + (size_t)(m0 + g + 8) * Dd + 2 * t4;
    #pragma unroll
    for (int nf = 0; nf < 16; nf++) {
        float2 w0 = make_float2(o[nf][0] * inv0, o[nf][1] * inv0);
        float2 w1 = make_float2(o[nf][2] * inv1, o[nf][3] * inv1);
        *(float2*)&o0[nf * 8] = w0;
        *(float2*)&o1[nf * 8] = w1;
    }
}

extern "C" void kernel_launch(void* const* d_in, const int* in_sizes, int n_in,
                              void* d_out, int out_size) {
    const float* q = (const float*)d_in[0];
    const float* k = (const float*)d_in[1];
    const float* v = (const float*)d_in[2];
    const unsigned char* mask = (const unsigned char*)d_in[3];
    const float* bias = (const float*)d_in[4];
    const int* off = (n_in > 5) ? (const int*)d_in[5] : nullptr;
    float* out = (float*)d_out;

    cudaFuncSetAttribute(attend_kernel,
                         cudaFuncAttributeMaxDynamicSharedMemorySize, SMEM_BYTES);

    prep_kernel<<<Bb, 256>>>(mask, off);
    dim3 grid(Ss / BM, Bb * Hh);
    attend_kernel<<<grid, NT, SMEM_BYTES>>>(q, k, v, bias, out);
}

// round 5
// speedup vs baseline: 2.4482x; 1.0426x over previous
#include <cuda_runtime.h>
#include <cuda_bf16.h>
#include <string.h>

#define Bb 2
#define Hh 16
#define Ss 2048
#define Dd 128
#define BM 128
#define BN 64
#define NT 256

// smem strides in bf16 elements (pad 8 -> conflict-free ldmatrix rows)
#define SQ 136
#define SK 136

// smem layout (bf16 elements)
#define OFF_QH 0
#define OFF_QL 17408              // 128*136
#define BUF0   34816              // K/V stage buffer 0
#define BUFSZ  34816              // per-buffer: KH,KL,VH,VL each 64*136=8704
#define KH_O   0
#define KL_O   8704
#define VH_O   17408
#define VL_O   26112
#define SMEM_ELEMS (BUF0 + 2*BUFSZ)     // 104448
#define SMEM_BYTES (SMEM_ELEMS*2)       // 208896

__device__ int g_len[Bb];
__device__ int g_off;

__global__ void prep_kernel(const unsigned char* __restrict__ mask, const int* offp) {
    int b = blockIdx.x;
    __shared__ int cnt;
    if (threadIdx.x == 0) cnt = 0;
    __syncthreads();
    bool w4 = (mask[1] == 0);
    int local = 0;
    for (int j = threadIdx.x; j < Ss; j += blockDim.x) {
        bool valid;
        if (w4) valid = (((const unsigned int*)mask)[(size_t)b * Ss + j] != 0u);
        else    valid = (mask[(size_t)b * Ss + j] != 0);
        local += valid ? 1 : 0;
    }
    atomicAdd(&cnt, local);
    __syncthreads();
    if (threadIdx.x == 0) {
        g_len[b] = cnt;
        if (b == 0) g_off = offp ? offp[0] : 0;
    }
}

__device__ __forceinline__ void split_pack(float x, float y, unsigned &hi, unsigned &lo) {
    __nv_bfloat162 hv = __floats2bfloat162_rn(x, y);
    float2 hf = __bfloat1622float2(hv);
    __nv_bfloat162 lv = __floats2bfloat162_rn(x - hf.x, y - hf.y);
    memcpy(&hi, &hv, 4);
    memcpy(&lo, &lv, 4);
}

#define LDSM4(r0,r1,r2,r3,addr) \
    asm volatile("ldmatrix.sync.aligned.m8n8.x4.shared.b16 {%0,%1,%2,%3}, [%4];\n" \
        : "=r"(r0),"=r"(r1),"=r"(r2),"=r"(r3) : "r"(addr))
#define LDSM4T(r0,r1,r2,r3,addr) \
    asm volatile("ldmatrix.sync.aligned.m8n8.x4.trans.shared.b16 {%0,%1,%2,%3}, [%4];\n" \
        : "=r"(r0),"=r"(r1),"=r"(r2),"=r"(r3) : "r"(addr))
#define MMA_BF16(c,a,b0,b1) \
    asm volatile("mma.sync.aligned.m16n8k16.row.col.f32.bf16.bf16.f32 " \
        "{%0,%1,%2,%3}, {%4,%5,%6,%7}, {%8,%9}, {%0,%1,%2,%3};\n" \
        : "+f"(c[0]),"+f"(c[1]),"+f"(c[2]),"+f"(c[3]) \
        : "r"(a[0]),"r"(a[1]),"r"(a[2]),"r"(a[3]),"r"(b0),"r"(b1))

__global__ __launch_bounds__(NT, 1)
void attend_kernel(const float* __restrict__ Q, const float* __restrict__ K,
                   const float* __restrict__ V, const float* __restrict__ Bias,
                   float* __restrict__ Out) {
    extern __shared__ unsigned short sm16[];

    const int tid = threadIdx.x;
    const int lane = tid & 31, w = tid >> 5;
    const int g = lane >> 2, t4 = lane & 3;
    const int lm = lane & 7, sel = lane >> 3;
    const int m0 = w * 16;

    const int bh = blockIdx.y;
    const int b = bh / Hh;
    const int h = bh - b * Hh;
    const int q0 = (gridDim.x - 1 - blockIdx.x) * BM;  // heavy CTAs first

    const int L = g_len[b];
    const int off = g_off;

    const float* qb = Q + ((size_t)bh * Ss + q0) * Dd;
    const float* kb = K + (size_t)bh * Ss * Dd;
    const float* vb = V + (size_t)bh * Ss * Dd;
    const float* bb = Bias + (size_t)h * Ss * Ss;
    float* ob = Out + ((size_t)bh * Ss + q0) * Dd;

    // ---- stage Q (128 x 128) as bf16 hi/lo ----
    #pragma unroll 4
    for (int t = tid; t < BM * (Dd / 4); t += NT) {
        int r = t >> 5, c4 = t & 31;
        float4 v = ((const float4*)(qb + (size_t)r * Dd))[c4];
        unsigned h0, l0, h1, l1;
        split_pack(v.x, v.y, h0, l0);
        split_pack(v.z, v.w, h1, l1);
        int base = r * SQ + c4 * 4;
        *(unsigned*)&sm16[OFF_QH + base]     = h0;
        *(unsigned*)&sm16[OFF_QH + base + 2] = h1;
        *(unsigned*)&sm16[OFF_QL + base]     = l0;
        *(unsigned*)&sm16[OFF_QL + base + 2] = l1;
    }

    // fragment lane addressing
    const unsigned smemB = (unsigned)__cvta_generic_to_shared(sm16);
    const int rowA  = m0 + lm + (sel & 1) * 8;
    const int rowBK = lm + ((sel & 2) >> 1) * 8;
    const int rowBV = lm + (sel & 1) * 8;
    const unsigned selA16 = ((sel & 2) >> 1) * 16;
    const unsigned selB16 = (sel & 1) * 16;

    const unsigned aQH = smemB + (OFF_QH + rowA * SQ) * 2 + selA16;
    const unsigned aQL = smemB + (OFF_QL + rowA * SQ) * 2 + selA16;
    const unsigned laneKH = (unsigned)(KH_O + rowBK * SK) * 2 + selB16;
    const unsigned laneKL = (unsigned)(KL_O + rowBK * SK) * 2 + selB16;
    const unsigned laneVH = (unsigned)(VH_O + rowBV * SK) * 2 + selA16;
    const unsigned laneVL = (unsigned)(VL_O + rowBV * SK) * 2 + selA16;

    // staging map: thread loads rows (w + 8i), float4-col = lane
    const int srow0 = w, scol = lane;

    float o[16][4];
    #pragma unroll
    for (int nf = 0; nf < 16; nf++)
        #pragma unroll
        for (int c = 0; c < 4; c++) o[nf][c] = 0.f;
    float mrow0 = -1e30f, mrow1 = -1e30f, lrow0 = 0.f, lrow1 = 0.f;

    const int i0 = q0 + m0 + g;
    const int i1 = i0 + 8;

    int maxj = q0 + BM - 1 - off;
    if (maxj > L - 1) maxj = L - 1;
    const int ntiles = (maxj >= 0) ? (maxj / BN + 1) : 0;

    const float scale = 0.08838834764831845f;  // 128^-0.5

    float4 kreg[8], vreg[8];

    // ---- prologue: load + stage tile 0 into buf0 ----
    if (ntiles > 0) {
        #pragma unroll
        for (int i = 0; i < 8; i++) {
            int r = srow0 + 8 * i;
            kreg[i] = __ldg((const float4*)(kb + (size_t)r * Dd) + scol);
            vreg[i] = __ldg((const float4*)(vb + (size_t)r * Dd) + scol);
        }
        #pragma unroll
        for (int i = 0; i < 8; i++) {
            int base = (srow0 + 8 * i) * SK + scol * 4;
            unsigned h0, l0, h1, l1;
            split_pack(kreg[i].x, kreg[i].y, h0, l0);
            split_pack(kreg[i].z, kreg[i].w, h1, l1);
            *(unsigned*)&sm16[BUF0 + KH_O + base]     = h0;
            *(unsigned*)&sm16[BUF0 + KH_O + base + 2] = h1;
            *(unsigned*)&sm16[BUF0 + KL_O + base]     = l0;
            *(unsigned*)&sm16[BUF0 + KL_O + base + 2] = l1;
            split_pack(vreg[i].x, vreg[i].y, h0, l0);
            split_pack(vreg[i].z, vreg[i].w, h1, l1);
            *(unsigned*)&sm16[BUF0 + VH_O + base]     = h0;
            *(unsigned*)&sm16[BUF0 + VH_O + base + 2] = h1;
            *(unsigned*)&sm16[BUF0 + VL_O + base]     = l0;
            *(unsigned*)&sm16[BUF0 + VL_O + base + 2] = l1;
        }
    }

    for (int t = 0; t < ntiles; ++t) {
        const int n0 = t * BN;
        const bool have_next = (t + 1 < ntiles);
        __syncthreads();  // buf[t&1] staged; buf[(t+1)&1] free

        // ---- issue global loads for tile t+1 (latency hidden under S-MMA) ----
        if (have_next) {
            const int nn0 = n0 + BN;
            #pragma unroll
            for (int i = 0; i < 8; i++) {
                int r = nn0 + srow0 + 8 * i;
                kreg[i] = __ldg((const float4*)(kb + (size_t)r * Dd) + scol);
                vreg[i] = __ldg((const float4*)(vb + (size_t)r * Dd) + scol);
            }
        }

        const unsigned bufE = BUF0 + (unsigned)(t & 1) * BUFSZ;
        const unsigned bufB = smemB + bufE * 2;
        const unsigned bKH = bufB + laneKH;
        const unsigned bKL = bufB + laneKL;
        const unsigned bVH = bufB + laneVH;
        const unsigned bVL = bufB + laneVL;

        // ---- S = Q @ K^T via bf16-split mma ----
        float acc[8][4];
        #pragma unroll
        for (int nf = 0; nf < 8; nf++)
            #pragma unroll
            for (int c = 0; c < 4; c++) acc[nf][c] = 0.f;

        #pragma unroll
        for (int kk = 0; kk < 8; kk++) {
            unsigned ah[4], al[4];
            LDSM4(ah[0], ah[1], ah[2], ah[3], aQH + kk * 32);
            LDSM4(al[0], al[1], al[2], al[3], aQL + kk * 32);
            #pragma unroll
            for (int nf2 = 0; nf2 < 4; nf2++) {
                unsigned bhr[4], blr[4];
                const unsigned boff = nf2 * (16 * SK * 2) + kk * 32;
                LDSM4(bhr[0], bhr[1], bhr[2], bhr[3], bKH + boff);
                LDSM4(blr[0], blr[1], blr[2], blr[3], bKL + boff);
                MMA_BF16(acc[2 * nf2],     ah, bhr[0], bhr[1]);
                MMA_BF16(acc[2 * nf2],     ah, blr[0], blr[1]);
                MMA_BF16(acc[2 * nf2],     al, bhr[0], bhr[1]);
                MMA_BF16(acc[2 * nf2 + 1], ah, bhr[2], bhr[3]);
                MMA_BF16(acc[2 * nf2 + 1], ah, blr[2], blr[3]);
                MMA_BF16(acc[2 * nf2 + 1], al, bhr[2], bhr[3]);
            }
        }

        // ---- stage tile t+1 into the other buffer ----
        if (have_next) {
            const unsigned nbufE = BUF0 + (unsigned)((t + 1) & 1) * BUFSZ;
            #pragma unroll
            for (int i = 0; i < 8; i++) {
                int base = (srow0 + 8 * i) * SK + scol * 4;
                unsigned h0, l0, h1, l1;
                split_pack(kreg[i].x, kreg[i].y, h0, l0);
                split_pack(kreg[i].z, kreg[i].w, h1, l1);
                *(unsigned*)&sm16[nbufE + KH_O + base]     = h0;
                *(unsigned*)&sm16[nbufE + KH_O + base + 2] = h1;
                *(unsigned*)&sm16[nbufE + KL_O + base]     = l0;
                *(unsigned*)&sm16[nbufE + KL_O + base + 2] = l1;
                split_pack(vreg[i].x, vreg[i].y, h0, l0);
                split_pack(vreg[i].z, vreg[i].w, h1, l1);
                *(unsigned*)&sm16[nbufE + VH_O + base]     = h0;
                *(unsigned*)&sm16[nbufE + VH_O + base + 2] = h1;
                *(unsigned*)&sm16[nbufE + VL_O + base]     = l0;
                *(unsigned*)&sm16[nbufE + VL_O + base + 2] = l1;
            }
        }

        // ---- scale + bias + mask ----
        const bool full = (n0 + BN - 1 <= q0 - off) && (n0 + BN <= L);
        #pragma unroll
        for (int nf = 0; nf < 8; nf++) {
            const int j0 = n0 + nf * 8 + 2 * t4;
            float2 bi0 = __ldg((const float2*)(bb + (size_t)i0 * Ss + j0));
            float2 bi1 = __ldg((const float2*)(bb + (size_t)i1 * Ss + j0));
            if (full) {
                acc[nf][0] = acc[nf][0] * scale + bi0.x;
                acc[nf][1] = acc[nf][1] * scale + bi0.y;
                acc[nf][2] = acc[nf][2] * scale + bi1.x;
                acc[nf][3] = acc[nf][3] * scale + bi1.y;
            } else {
                acc[nf][0] = (j0     <= i0 - off && j0     < L) ? acc[nf][0] * scale + bi0.x : -1e30f;
                acc[nf][1] = (j0 + 1 <= i0 - off && j0 + 1 < L) ? acc[nf][1] * scale + bi0.y : -1e30f;
                acc[nf][2] = (j0     <= i1 - off && j0     < L) ? acc[nf][2] * scale + bi1.x : -1e30f;
                acc[nf][3] = (j0 + 1 <= i1 - off && j0 + 1 < L) ? acc[nf][3] * scale + bi1.y : -1e30f;
            }
        }

        // ---- online softmax; P packed directly into A-fragment registers ----
        float mx0 = acc[0][0], mx1 = acc[0][2];
        #pragma unroll
        for (int nf = 0; nf < 8; nf++) {
            mx0 = fmaxf(mx0, fmaxf(acc[nf][0], acc[nf][1]));
            mx1 = fmaxf(mx1, fmaxf(acc[nf][2], acc[nf][3]));
        }
        mx0 = fmaxf(mx0, __shfl_xor_sync(0xFFFFFFFFu, mx0, 1));
        mx0 = fmaxf(mx0, __shfl_xor_sync(0xFFFFFFFFu, mx0, 2));
        mx1 = fmaxf(mx1, __shfl_xor_sync(0xFFFFFFFFu, mx1, 1));
        mx1 = fmaxf(mx1, __shfl_xor_sync(0xFFFFFFFFu, mx1, 2));
        const float mn0 = fmaxf(mrow0, mx0);
        const float mn1 = fmaxf(mrow1, mx1);
        const float alpha0 = __expf(mrow0 - mn0);
        const float alpha1 = __expf(mrow1 - mn1);
        float sum0 = 0.f, sum1 = 0.f;

        unsigned ph01[8], pl01[8], ph23[8], pl23[8];
        #pragma unroll
        for (int nf = 0; nf < 8; nf++) {
            float p00 = __expf(acc[nf][0] - mn0);
            float p01 = __expf(acc[nf][1] - mn0);
            float p10 = __expf(acc[nf][2] - mn1);
            float p11 = __expf(acc[nf][3] - mn1);
            sum0 += p00 + p01;
            sum1 += p10 + p11;
            split_pack(p00, p01, ph01[nf], pl01[nf]);
            split_pack(p10, p11, ph23[nf], pl23[nf]);
        }
        sum0 += __shfl_xor_sync(0xFFFFFFFFu, sum0, 1);
        sum0 += __shfl_xor_sync(0xFFFFFFFFu, sum0, 2);
        sum1 += __shfl_xor_sync(0xFFFFFFFFu, sum1, 1);
        sum1 += __shfl_xor_sync(0xFFFFFFFFu, sum1, 2);
        lrow0 = lrow0 * alpha0 + sum0;
        lrow1 = lrow1 * alpha1 + sum1;
        mrow0 = mn0; mrow1 = mn1;

        #pragma unroll
        for (int nf = 0; nf < 16; nf++) {
            o[nf][0] *= alpha0; o[nf][1] *= alpha0;
            o[nf][2] *= alpha1; o[nf][3] *= alpha1;
        }

        // ---- O += P @ V (A-fragments straight from registers) ----
        #pragma unroll
        for (int kk = 0; kk < 4; kk++) {
            unsigned ah[4], al[4];
            ah[0] = ph01[2 * kk];     al[0] = pl01[2 * kk];
            ah[1] = ph23[2 * kk];     al[1] = pl23[2 * kk];
            ah[2] = ph01[2 * kk + 1]; al[2] = pl01[2 * kk + 1];
            ah[3] = ph23[2 * kk + 1]; al[3] = pl23[2 * kk + 1];
            #pragma unroll
            for (int nf2 = 0; nf2 < 8; nf2++) {
                unsigned bhr[4], blr[4];
                const unsigned boff = kk * (16 * SK * 2) + nf2 * 32;
                LDSM4T(bhr[0], bhr[1], bhr[2], bhr[3], bVH + boff);
                LDSM4T(blr[0], blr[1], blr[2], blr[3], bVL + boff);
                MMA_BF16(o[2 * nf2],     ah, bhr[0], bhr[1]);
                MMA_BF16(o[2 * nf2],     ah, blr[0], blr[1]);
                MMA_BF16(o[2 * nf2],     al, bhr[0], bhr[1]);
                MMA_BF16(o[2 * nf2 + 1], ah, bhr[2], bhr[3]);
                MMA_BF16(o[2 * nf2 + 1], ah, blr[2], blr[3]);
                MMA_BF16(o[2 * nf2 + 1], al, bhr[2], bhr[3]);
            }
        }
    }

    // ---- normalize + write ----
    const float inv0 = (lrow0 > 0.f) ? (1.f / lrow0) : 0.f;
    const float inv1 = (lrow1 > 0.f) ? (1.f / lrow1) : 0.f;
    float* o0 = ob + (size_t)(m0 + g) * Dd + 2 * t4;
    float* o1 = ob + (size_t)(m0 + g + 8) * Dd + 2 * t4;
    #pragma unroll
    for (int nf = 0; nf < 16; nf++) {
        float2 w0 = make_float2(o[nf][0] * inv0, o[nf][1] * inv0);
        float2 w1 = make_float2(o[nf][2] * inv1, o[nf][3] * inv1);
        *(float2*)&o0[nf * 8] = w0;
        *(float2*)&o1[nf * 8] = w1;
    }
}

extern "C" void kernel_launch(void* const* d_in, const int* in_sizes, int n_in,
                              void* d_out, int out_size) {
    const float* q = (const float*)d_in[0];
    const float* k = (const float*)d_in[1];
    const float* v = (const float*)d_in[2];
    const unsigned char* mask = (const unsigned char*)d_in[3];
    const float* bias = (const float*)d_in[4];
    const int* off = (n_in > 5) ? (const int*)d_in[5] : nullptr;
    float* out = (float*)d_out;

    cudaFuncSetAttribute(attend_kernel,
                         cudaFuncAttributeMaxDynamicSharedMemorySize, SMEM_BYTES);

    prep_kernel<<<Bb, 256>>>(mask, off);
    dim3 grid(Ss / BM, Bb * Hh);
    attend_kernel<<<grid, NT, SMEM_BYTES>>>(q, k, v, bias, out);
}

// round 6
// speedup vs baseline: 2.4593x; 1.0045x over previous
#include <cuda_runtime.h>
#include <cuda_bf16.h>
#include <string.h>

#define Bb 2
#define Hh 16
#define Ss 2048
#define Dd 128
#define BM 128
#define BN 64
#define NT 256

// smem strides in bf16 elements (pad 8 -> conflict-free ldmatrix rows)
#define SQ 136
#define SK 136

// smem layout (bf16 elements)
#define OFF_QH 0
#define OFF_QL 17408              // 128*136
#define BUF0   34816              // K/V stage buffer 0
#define BUFSZ  34816              // per-buffer: KH,KL,VH,VL each 64*136=8704
#define KH_O   0
#define KL_O   8704
#define VH_O   17408
#define VL_O   26112
#define SMEM_ELEMS (BUF0 + 2*BUFSZ)     // 104448
#define SMEM_BYTES (SMEM_ELEMS*2)       // 208896

__device__ int g_len[Bb];
__device__ int g_off;

__global__ void prep_kernel(const unsigned char* __restrict__ mask, const int* offp) {
    int b = blockIdx.x;
    __shared__ int cnt;
    if (threadIdx.x == 0) cnt = 0;
    __syncthreads();
    bool w4 = (mask[1] == 0);
    int local = 0;
    for (int j = threadIdx.x; j < Ss; j += blockDim.x) {
        bool valid;
        if (w4) valid = (((const unsigned int*)mask)[(size_t)b * Ss + j] != 0u);
        else    valid = (mask[(size_t)b * Ss + j] != 0);
        local += valid ? 1 : 0;
    }
    atomicAdd(&cnt, local);
    __syncthreads();
    if (threadIdx.x == 0) {
        g_len[b] = cnt;
        if (b == 0) g_off = offp ? offp[0] : 0;
    }
}

__device__ __forceinline__ void split_pack(float x, float y, unsigned &hi, unsigned &lo) {
    __nv_bfloat162 hv = __floats2bfloat162_rn(x, y);
    float2 hf = __bfloat1622float2(hv);
    __nv_bfloat162 lv = __floats2bfloat162_rn(x - hf.x, y - hf.y);
    memcpy(&hi, &hv, 4);
    memcpy(&lo, &lv, 4);
}

#define LDSM4(r0,r1,r2,r3,addr) \
    asm volatile("ldmatrix.sync.aligned.m8n8.x4.shared.b16 {%0,%1,%2,%3}, [%4];\n" \
        : "=r"(r0),"=r"(r1),"=r"(r2),"=r"(r3) : "r"(addr))
#define LDSM4T(r0,r1,r2,r3,addr) \
    asm volatile("ldmatrix.sync.aligned.m8n8.x4.trans.shared.b16 {%0,%1,%2,%3}, [%4];\n" \
        : "=r"(r0),"=r"(r1),"=r"(r2),"=r"(r3) : "r"(addr))
#define MMA_BF16(c,a,b0,b1) \
    asm volatile("mma.sync.aligned.m16n8k16.row.col.f32.bf16.bf16.f32 " \
        "{%0,%1,%2,%3}, {%4,%5,%6,%7}, {%8,%9}, {%0,%1,%2,%3};\n" \
        : "+f"(c[0]),"+f"(c[1]),"+f"(c[2]),"+f"(c[3]) \
        : "r"(a[0]),"r"(a[1]),"r"(a[2]),"r"(a[3]),"r"(b0),"r"(b1))

__global__ __launch_bounds__(NT, 1)
void attend_kernel(const float* __restrict__ Q, const float* __restrict__ K,
                   const float* __restrict__ V, const float* __restrict__ Bias,
                   float* __restrict__ Out) {
    extern __shared__ unsigned short sm16[];

    const int tid = threadIdx.x;
    const int lane = tid & 31, w = tid >> 5;
    const int g = lane >> 2, t4 = lane & 3;
    const int lm = lane & 7, sel = lane >> 3;
    const int m0 = w * 16;

    const int bh = blockIdx.y;
    const int b = bh / Hh;
    const int h = bh - b * Hh;
    const int q0 = (gridDim.x - 1 - blockIdx.x) * BM;  // heavy CTAs first

    const int L = g_len[b];
    const int off = g_off;

    const float* qb = Q + ((size_t)bh * Ss + q0) * Dd;
    const float* kb = K + (size_t)bh * Ss * Dd;
    const float* vb = V + (size_t)bh * Ss * Dd;
    const float* bb = Bias + (size_t)h * Ss * Ss;
    float* ob = Out + ((size_t)bh * Ss + q0) * Dd;

    // ---- stage Q (128 x 128) as bf16 hi/lo ----
    #pragma unroll 4
    for (int t = tid; t < BM * (Dd / 4); t += NT) {
        int r = t >> 5, c4 = t & 31;
        float4 v = ((const float4*)(qb + (size_t)r * Dd))[c4];
        unsigned h0, l0, h1, l1;
        split_pack(v.x, v.y, h0, l0);
        split_pack(v.z, v.w, h1, l1);
        int base = r * SQ + c4 * 4;
        *(unsigned*)&sm16[OFF_QH + base]     = h0;
        *(unsigned*)&sm16[OFF_QH + base + 2] = h1;
        *(unsigned*)&sm16[OFF_QL + base]     = l0;
        *(unsigned*)&sm16[OFF_QL + base + 2] = l1;
    }

    // fragment lane addressing
    const unsigned smemB = (unsigned)__cvta_generic_to_shared(sm16);
    const int rowA  = m0 + lm + (sel & 1) * 8;
    const int rowBK = lm + ((sel & 2) >> 1) * 8;
    const int rowBV = lm + (sel & 1) * 8;
    const unsigned selA16 = ((sel & 2) >> 1) * 16;
    const unsigned selB16 = (sel & 1) * 16;

    const unsigned aQH = smemB + (OFF_QH + rowA * SQ) * 2 + selA16;
    const unsigned aQL = smemB + (OFF_QL + rowA * SQ) * 2 + selA16;
    const unsigned laneKH = (unsigned)(KH_O + rowBK * SK) * 2 + selB16;
    const unsigned laneKL = (unsigned)(KL_O + rowBK * SK) * 2 + selB16;
    const unsigned laneVH = (unsigned)(VH_O + rowBV * SK) * 2 + selA16;
    const unsigned laneVL = (unsigned)(VL_O + rowBV * SK) * 2 + selA16;

    // staging map: thread loads rows (w + 8i), float4-col = lane
    const int srow0 = w, scol = lane;

    float o[16][4];
    #pragma unroll
    for (int nf = 0; nf < 16; nf++)
        #pragma unroll
        for (int c = 0; c < 4; c++) o[nf][c] = 0.f;
    float mrow0 = -1e30f, mrow1 = -1e30f, lrow0 = 0.f, lrow1 = 0.f;

    const int i0 = q0 + m0 + g;
    const int i1 = i0 + 8;

    int maxj = q0 + BM - 1 - off;
    if (maxj > L - 1) maxj = L - 1;
    const int ntiles = (maxj >= 0) ? (maxj / BN + 1) : 0;

    const float scale = 0.08838834764831845f;  // 128^-0.5

    float4 kreg[8], vreg[8];

    // ---- prologue: load + stage tile 0 into buf0 ----
    if (ntiles > 0) {
        #pragma unroll
        for (int i = 0; i < 8; i++) {
            int r = srow0 + 8 * i;
            kreg[i] = __ldg((const float4*)(kb + (size_t)r * Dd) + scol);
            vreg[i] = __ldg((const float4*)(vb + (size_t)r * Dd) + scol);
        }
        #pragma unroll
        for (int i = 0; i < 8; i++) {
            int base = (srow0 + 8 * i) * SK + scol * 4;
            unsigned h0, l0, h1, l1;
            split_pack(kreg[i].x, kreg[i].y, h0, l0);
            split_pack(kreg[i].z, kreg[i].w, h1, l1);
            *(unsigned*)&sm16[BUF0 + KH_O + base]     = h0;
            *(unsigned*)&sm16[BUF0 + KH_O + base + 2] = h1;
            *(unsigned*)&sm16[BUF0 + KL_O + base]     = l0;
            *(unsigned*)&sm16[BUF0 + KL_O + base + 2] = l1;
            split_pack(vreg[i].x, vreg[i].y, h0, l0);
            split_pack(vreg[i].z, vreg[i].w, h1, l1);
            *(unsigned*)&sm16[BUF0 + VH_O + base]     = h0;
            *(unsigned*)&sm16[BUF0 + VH_O + base + 2] = h1;
            *(unsigned*)&sm16[BUF0 + VL_O + base]     = l0;
            *(unsigned*)&sm16[BUF0 + VL_O + base + 2] = l1;
        }
    }

    for (int t = 0; t < ntiles; ++t) {
        const int n0 = t * BN;
        const bool have_next = (t + 1 < ntiles);
        __syncthreads();  // buf[t&1] staged; buf[(t+1)&1] free

        // ---- issue global loads for tile t+1 (latency hidden under S-MMA) ----
        if (have_next) {
            const int nn0 = n0 + BN;
            #pragma unroll
            for (int i = 0; i < 8; i++) {
                int r = nn0 + srow0 + 8 * i;
                kreg[i] = __ldg((const float4*)(kb + (size_t)r * Dd) + scol);
                vreg[i] = __ldg((const float4*)(vb + (size_t)r * Dd) + scol);
            }
        }

        const unsigned bufE = BUF0 + (unsigned)(t & 1) * BUFSZ;
        const unsigned bufB = smemB + bufE * 2;
        const unsigned bKH = bufB + laneKH;
        const unsigned bKL = bufB + laneKL;
        const unsigned bVH = bufB + laneVH;
        const unsigned bVL = bufB + laneVL;

        // ---- S = Q @ K^T via bf16-split mma ----
        float acc[8][4];
        #pragma unroll
        for (int nf = 0; nf < 8; nf++)
            #pragma unroll
            for (int c = 0; c < 4; c++) acc[nf][c] = 0.f;

        #pragma unroll
        for (int kk = 0; kk < 8; kk++) {
            unsigned ah[4], al[4];
            LDSM4(ah[0], ah[1], ah[2], ah[3], aQH + kk * 32);
            LDSM4(al[0], al[1], al[2], al[3], aQL + kk * 32);
            #pragma unroll
            for (int nf2 = 0; nf2 < 4; nf2++) {
                unsigned bhr[4], blr[4];
                const unsigned boff = nf2 * (16 * SK * 2) + kk * 32;
                LDSM4(bhr[0], bhr[1], bhr[2], bhr[3], bKH + boff);
                LDSM4(blr[0], blr[1], blr[2], blr[3], bKL + boff);
                MMA_BF16(acc[2 * nf2],     ah, bhr[0], bhr[1]);
                MMA_BF16(acc[2 * nf2],     ah, blr[0], blr[1]);
                MMA_BF16(acc[2 * nf2],     al, bhr[0], bhr[1]);
                MMA_BF16(acc[2 * nf2 + 1], ah, bhr[2], bhr[3]);
                MMA_BF16(acc[2 * nf2 + 1], ah, blr[2], blr[3]);
                MMA_BF16(acc[2 * nf2 + 1], al, bhr[2], bhr[3]);
            }
        }

        // ---- stage tile t+1 into the other buffer ----
        if (have_next) {
            const unsigned nbufE = BUF0 + (unsigned)((t + 1) & 1) * BUFSZ;
            #pragma unroll
            for (int i = 0; i < 8; i++) {
                int base = (srow0 + 8 * i) * SK + scol * 4;
                unsigned h0, l0, h1, l1;
                split_pack(kreg[i].x, kreg[i].y, h0, l0);
                split_pack(kreg[i].z, kreg[i].w, h1, l1);
                *(unsigned*)&sm16[nbufE + KH_O + base]     = h0;
                *(unsigned*)&sm16[nbufE + KH_O + base + 2] = h1;
                *(unsigned*)&sm16[nbufE + KL_O + base]     = l0;
                *(unsigned*)&sm16[nbufE + KL_O + base + 2] = l1;
                split_pack(vreg[i].x, vreg[i].y, h0, l0);
                split_pack(vreg[i].z, vreg[i].w, h1, l1);
                *(unsigned*)&sm16[nbufE + VH_O + base]     = h0;
                *(unsigned*)&sm16[nbufE + VH_O + base + 2] = h1;
                *(unsigned*)&sm16[nbufE + VL_O + base]     = l0;
                *(unsigned*)&sm16[nbufE + VL_O + base + 2] = l1;
            }
        }

        // ---- scale + bias + mask ----
        const bool full = (n0 + BN - 1 <= q0 - off) && (n0 + BN <= L);
        #pragma unroll
        for (int nf = 0; nf < 8; nf++) {
            const int j0 = n0 + nf * 8 + 2 * t4;
            float2 bi0 = __ldg((const float2*)(bb + (size_t)i0 * Ss + j0));
            float2 bi1 = __ldg((const float2*)(bb + (size_t)i1 * Ss + j0));
            if (full) {
                acc[nf][0] = acc[nf][0] * scale + bi0.x;
                acc[nf][1] = acc[nf][1] * scale + bi0.y;
                acc[nf][2] = acc[nf][2] * scale + bi1.x;
                acc[nf][3] = acc[nf][3] * scale + bi1.y;
            } else {
                acc[nf][0] = (j0     <= i0 - off && j0     < L) ? acc[nf][0] * scale + bi0.x : -1e30f;
                acc[nf][1] = (j0 + 1 <= i0 - off && j0 + 1 < L) ? acc[nf][1] * scale + bi0.y : -1e30f;
                acc[nf][2] = (j0     <= i1 - off && j0     < L) ? acc[nf][2] * scale + bi1.x : -1e30f;
                acc[nf][3] = (j0 + 1 <= i1 - off && j0 + 1 < L) ? acc[nf][3] * scale + bi1.y : -1e30f;
            }
        }

        // ---- online softmax; P packed directly into A-fragment registers ----
        float mx0 = acc[0][0], mx1 = acc[0][2];
        #pragma unroll
        for (int nf = 0; nf < 8; nf++) {
            mx0 = fmaxf(mx0, fmaxf(acc[nf][0], acc[nf][1]));
            mx1 = fmaxf(mx1, fmaxf(acc[nf][2], acc[nf][3]));
        }
        mx0 = fmaxf(mx0, __shfl_xor_sync(0xFFFFFFFFu, mx0, 1));
        mx0 = fmaxf(mx0, __shfl_xor_sync(0xFFFFFFFFu, mx0, 2));
        mx1 = fmaxf(mx1, __shfl_xor_sync(0xFFFFFFFFu, mx1, 1));
        mx1 = fmaxf(mx1, __shfl_xor_sync(0xFFFFFFFFu, mx1, 2));
        const float mn0 = fmaxf(mrow0, mx0);
        const float mn1 = fmaxf(mrow1, mx1);
        const float alpha0 = __expf(mrow0 - mn0);
        const float alpha1 = __expf(mrow1 - mn1);
        float sum0 = 0.f, sum1 = 0.f;

        unsigned ph01[8], pl01[8], ph23[8], pl23[8];
        #pragma unroll
        for (int nf = 0; nf < 8; nf++) {
            float p00 = __expf(acc[nf][0] - mn0);
            float p01 = __expf(acc[nf][1] - mn0);
            float p10 = __expf(acc[nf][2] - mn1);
            float p11 = __expf(acc[nf][3] - mn1);
            sum0 += p00 + p01;
            sum1 += p10 + p11;
            split_pack(p00, p01, ph01[nf], pl01[nf]);
            split_pack(p10, p11, ph23[nf], pl23[nf]);
        }
        sum0 += __shfl_xor_sync(0xFFFFFFFFu, sum0, 1);
        sum0 += __shfl_xor_sync(0xFFFFFFFFu, sum0, 2);
        sum1 += __shfl_xor_sync(0xFFFFFFFFu, sum1, 1);
        sum1 += __shfl_xor_sync(0xFFFFFFFFu, sum1, 2);
        lrow0 = lrow0 * alpha0 + sum0;
        lrow1 = lrow1 * alpha1 + sum1;
        mrow0 = mn0; mrow1 = mn1;

        #pragma unroll
        for (int nf = 0; nf < 16; nf++) {
            o[nf][0] *= alpha0; o[nf][1] *= alpha0;
            o[nf][2] *= alpha1; o[nf][3] *= alpha1;
        }

        // ---- O += P @ V (A-fragments straight from registers) ----
        #pragma unroll
        for (int kk = 0; kk < 4; kk++) {
            unsigned ah[4], al[4];
            ah[0] = ph01[2 * kk];     al[0] = pl01[2 * kk];
            ah[1] = ph23[2 * kk];     al[1] = pl23[2 * kk];
            ah[2] = ph01[2 * kk + 1]; al[2] = pl01[2 * kk + 1];
            ah[3] = ph23[2 * kk + 1]; al[3] = pl23[2 * kk + 1];
            #pragma unroll
            for (int nf2 = 0; nf2 < 8; nf2++) {
                unsigned bhr[4], blr[4];
                const unsigned boff = kk * (16 * SK * 2) + nf2 * 32;
                LDSM4T(bhr[0], bhr[1], bhr[2], bhr[3], bVH + boff);
                LDSM4T(blr[0], blr[1], blr[2], blr[3], bVL + boff);
                MMA_BF16(o[2 * nf2],     ah, bhr[0], bhr[1]);
                MMA_BF16(o[2 * nf2],     ah, blr[0], blr[1]);
                MMA_BF16(o[2 * nf2],     al, bhr[0], bhr[1]);
                MMA_BF16(o[2 * nf2 + 1], ah, bhr[2], bhr[3]);
                MMA_BF16(o[2 * nf2 + 1], ah, blr[2], blr[3]);
                MMA_BF16(o[2 * nf2 + 1], al, bhr[2], bhr[3]);
            }
        }
    }

    // ---- normalize + write ----
    const float inv0 = (lrow0 > 0.f) ? (1.f / lrow0) : 0.f;
    const float inv1 = (lrow1 > 0.f) ? (1.f / lrow1) : 0.f;
    float* o0 = ob + (size_t)(m0 + g) * Dd + 2 * t4;
    float* o1 = ob + (size_t)(m0 + g + 8) * Dd + 2 * t4;
    #pragma unroll
    for (int nf = 0; nf < 16; nf++) {
        float2 w0 = make_float2(o[nf][0] * inv0, o[nf][1] * inv0);
        float2 w1 = make_float2(o[nf][2] * inv1, o[nf][3] * inv1);
        *(float2*)&o0[nf * 8] = w0;
        *(float2*)&o1[nf * 8] = w1;
    }
}

extern "C" void kernel_launch(void* const* d_in, const int* in_sizes, int n_in,
                              void* d_out, int out_size) {
    const float* q = (const float*)d_in[0];
    const float* k = (const float*)d_in[1];
    const float* v = (const float*)d_in[2];
    const unsigned char* mask = (const unsigned char*)d_in[3];
    const float* bias = (const float*)d_in[4];
    const int* off = (n_in > 5) ? (const int*)d_in[5] : nullptr;
    float* out = (float*)d_out;

    cudaFuncSetAttribute(attend_kernel,
                         cudaFuncAttributeMaxDynamicSharedMemorySize, SMEM_BYTES);

    prep_kernel<<<Bb, 256>>>(mask, off);
    dim3 grid(Ss / BM, Bb * Hh);
    attend_kernel<<<grid, NT, SMEM_BYTES>>>(q, k, v, bias, out);
}